// round 2
// baseline (speedup 1.0000x reference)
#include <cuda_runtime.h>

// G=1024 groups, K=16 agents/group, T=32, D=64, N=16384
// out[n,t,0:64]  = group mean of h ; out[n,t,64:128] = h
// h = fc2(relu(LN(fc1(x))))
#define GRP   1024
#define AG    16
#define TT    32
#define DD    64
#define ROWSG 512
#define TILE_R 64
#define N_TILES 8

typedef unsigned long long u64t;

// float offset of 16B chunk `kk` (0..15) in row `row` of a 64-wide tile,
// XOR-swizzled so per-TX row loads spread across bank groups.
#define SWOFF(row, kk) (((row) << 6) + ((((kk) ^ (((row) >> 2) & 7))) << 2))

__device__ __forceinline__ void ffma2(u64t& d, u64t a, u64t b) {
    asm("fma.rn.f32x2 %0, %1, %2, %3;" : "=l"(d) : "l"(a), "l"(b), "l"(d));
}
__device__ __forceinline__ u64t pk(float x, float y) {
    u64t r; asm("mov.b64 %0, {%1, %2};" : "=l"(r) : "f"(x), "f"(y)); return r;
}
__device__ __forceinline__ float2 upk(u64t v) {
    float2 r; asm("mov.b64 {%0, %1}, %2;" : "=f"(r.x), "=f"(r.y) : "l"(v)); return r;
}

// 64x64x64 tile GEMM, f32x2-packed over k.
// act: swizzled [64][64] activation tile; ws: swizzled [64 j][64 k] weights.
__device__ __forceinline__ void mm2(const float* __restrict__ act,
                                    const float* __restrict__ ws,
                                    int r0, int j0, float cout[4][4]) {
    u64t acc[4][4];
    #pragma unroll
    for (int i = 0; i < 4; i++)
        #pragma unroll
        for (int j = 0; j < 4; j++) acc[i][j] = 0ull;

    #pragma unroll
    for (int kk = 0; kk < 16; kk++) {
        float4 a[4], b[4];
        #pragma unroll
        for (int i = 0; i < 4; i++)
            a[i] = *(const float4*)(act + SWOFF(r0 + i, kk));
        #pragma unroll
        for (int j = 0; j < 4; j++)
            b[j] = *(const float4*)(ws + SWOFF(j0 + j, kk));
        #pragma unroll
        for (int i = 0; i < 4; i++) {
            u64t alo = pk(a[i].x, a[i].y);
            u64t ahi = pk(a[i].z, a[i].w);
            #pragma unroll
            for (int j = 0; j < 4; j++) {
                ffma2(acc[i][j], alo, pk(b[j].x, b[j].y));
                ffma2(acc[i][j], ahi, pk(b[j].z, b[j].w));
            }
        }
    }
    #pragma unroll
    for (int i = 0; i < 4; i++)
        #pragma unroll
        for (int j = 0; j < 4; j++) {
            float2 t = upk(acc[i][j]);
            cout[i][j] = t.x + t.y;
        }
}

__global__ void __launch_bounds__(256, 3)
subgraph_fused_kernel(const float* __restrict__ x,
                      const float* __restrict__ w1g, const float* __restrict__ b1g,
                      const float* __restrict__ lnwg, const float* __restrict__ lnbg,
                      const float* __restrict__ w2g, const float* __restrict__ b2g,
                      float* __restrict__ out) {
    extern __shared__ float sm[];
    float* xs   = sm;                 // 4096 (x tile, later h2 tile), swizzled
    float* ys   = xs + 4096;          // 4096 (act tile), swizzled
    float* w1s  = ys + 4096;          // 4096, native [j][k], swizzled
    float* w2s  = w1s + 4096;         // 4096
    float* sums = w2s + 4096;         // 2048 ([32 t][64 d])
    float* b1s  = sums + TT * DD;     // 64
    float* b2s  = b1s + DD;           // 64
    float* lnws = b2s + DD;           // 64
    float* lnbs = lnws + DD;          // 64

    const int tid = threadIdx.x;
    const int g   = blockIdx.x;

    // ---- stage weights (native [j][k], chunk-swizzled), biases; zero sums ----
    #pragma unroll
    for (int v = 0; v < 16; v++) {
        int lin = tid + v * 256;          // 0..4095
        int j = lin >> 6, k = lin & 63;
        int off = (j << 6) + ((((k >> 2) ^ ((j >> 2) & 7))) << 2) + (k & 3);
        w1s[off] = w1g[lin];
        w2s[off] = w2g[lin];
    }
    if (tid < DD) {
        b1s[tid] = b1g[tid];  b2s[tid] = b2g[tid];
        lnws[tid] = lnwg[tid]; lnbs[tid] = lnbg[tid];
    }
    #pragma unroll
    for (int v = 0; v < 8; v++) sums[tid + v * 256] = 0.f;
    __syncthreads();

    const int TX = tid & 15;
    const int TY = tid >> 4;
    const int j0 = TX * 4;
    const int r0 = TY * 4;

    const float* xg   = x + (size_t)g * (ROWSG * DD);
    float*       outg = out + (size_t)g * (ROWSG * 2 * DD);

    for (int it = 0; it < N_TILES; ++it) {
        // ---- stage x tile into xs (swizzled) ----
        const float4* xt = (const float4*)(xg + it * TILE_R * DD);
        #pragma unroll
        for (int v = 0; v < 4; v++) {
            int lin = tid + v * 256;      // chunk id 0..1023
            int row = lin >> 4, kk = lin & 15;
            *(float4*)(xs + SWOFF(row, kk)) = xt[lin];
        }
        __syncthreads();                  // A: xs staged

        // ---- GEMM1 + bias + register LayerNorm + ReLU ----
        float c[4][4];
        mm2(xs, w1s, r0, j0, c);

        float4 b1v = *(const float4*)(b1s + j0);
        float4 lw  = *(const float4*)(lnws + j0);
        float4 lb  = *(const float4*)(lnbs + j0);

        float h[4][4], s[4], q[4];
        #pragma unroll
        for (int i = 0; i < 4; i++) {
            h[i][0] = c[i][0] + b1v.x;
            h[i][1] = c[i][1] + b1v.y;
            h[i][2] = c[i][2] + b1v.z;
            h[i][3] = c[i][3] + b1v.w;
            s[i] = h[i][0] + h[i][1] + h[i][2] + h[i][3];
            q[i] = h[i][0]*h[i][0] + h[i][1]*h[i][1]
                 + h[i][2]*h[i][2] + h[i][3]*h[i][3];
        }
        #pragma unroll
        for (int m = 1; m <= 8; m <<= 1) {
            #pragma unroll
            for (int i = 0; i < 4; i++) {
                s[i] += __shfl_xor_sync(0xffffffffu, s[i], m);
                q[i] += __shfl_xor_sync(0xffffffffu, q[i], m);
            }
        }
        // act -> ys (ys free: last readers finished before previous tile's sync C)
        #pragma unroll
        for (int i = 0; i < 4; i++) {
            float mu  = s[i] * (1.f / 64.f);
            float var = q[i] * (1.f / 64.f) - mu * mu;
            float inv = rsqrtf(var + 1e-5f);
            float4 o;
            o.x = fmaxf(fmaf((h[i][0] - mu) * inv, lw.x, lb.x), 0.f);
            o.y = fmaxf(fmaf((h[i][1] - mu) * inv, lw.y, lb.y), 0.f);
            o.z = fmaxf(fmaf((h[i][2] - mu) * inv, lw.z, lb.z), 0.f);
            o.w = fmaxf(fmaf((h[i][3] - mu) * inv, lw.w, lb.w), 0.f);
            *(float4*)(ys + SWOFF(r0 + i, TX)) = o;
        }
        __syncthreads();                  // B: act visible; xs reads all done

        // ---- GEMM2 + bias; write h to gmem and stage into xs ----
        mm2(ys, w2s, r0, j0, c);
        float4 b2v = *(const float4*)(b2s + j0);
        #pragma unroll
        for (int i = 0; i < 4; i++) {
            float4 v;
            v.x = c[i][0] + b2v.x;
            v.y = c[i][1] + b2v.y;
            v.z = c[i][2] + b2v.z;
            v.w = c[i][3] + b2v.w;
            int r = it * TILE_R + r0 + i;
            *(float4*)(outg + (size_t)r * (2 * DD) + DD + j0) = v;
            *(float4*)(xs + SWOFF(r0 + i, TX)) = v;   // xs free since sync B
        }
        __syncthreads();                  // C: h2 tile visible

        // ---- accumulate group sums (agents 2it, 2it+1) ----
        #pragma unroll
        for (int v = 0; v < 2; v++) {
            int f  = tid + v * 256;       // chunk 0..511
            int t  = f >> 4, kk = f & 15;
            float4 a  = *(const float4*)(xs + SWOFF(t, kk));
            float4 bb = *(const float4*)(xs + SWOFF(t + 32, kk));
            float4 sv = *(const float4*)(sums + t * DD + kk * 4);
            sv.x += a.x + bb.x; sv.y += a.y + bb.y;
            sv.z += a.z + bb.z; sv.w += a.w + bb.w;
            *(float4*)(sums + t * DD + kk * 4) = sv;
        }
        __syncthreads();                  // D: sums updated, xs free for next stage
    }

    // ---- write group means for all 16 agents ----
    #pragma unroll
    for (int v = 0; v < 2; v++) {
        int f  = tid + v * 256;
        int t  = f >> 4, kk = f & 15;
        float4 sv = *(const float4*)(sums + t * DD + kk * 4);
        sv.x *= 0.0625f; sv.y *= 0.0625f; sv.z *= 0.0625f; sv.w *= 0.0625f;
        #pragma unroll
        for (int k = 0; k < AG; k++)
            *(float4*)(outg + (size_t)(k * TT + t) * (2 * DD) + kk * 4) = sv;
    }
}

extern "C" void kernel_launch(void* const* d_in, const int* in_sizes, int n_in,
                              void* d_out, int out_size) {
    const float* x    = (const float*)d_in[0];
    const float* fc1w = (const float*)d_in[3];
    const float* fc1b = (const float*)d_in[4];
    const float* lnw  = (const float*)d_in[5];
    const float* lnb  = (const float*)d_in[6];
    const float* fc2w = (const float*)d_in[7];
    const float* fc2b = (const float*)d_in[8];
    float* out = (float*)d_out;

    const int smem_bytes = (4 * 4096 + TT * DD + 4 * DD) * (int)sizeof(float); // 74752
    cudaFuncSetAttribute(subgraph_fused_kernel,
                         cudaFuncAttributeMaxDynamicSharedMemorySize, smem_bytes);
    subgraph_fused_kernel<<<GRP, 256, smem_bytes>>>(x, fc1w, fc1b, lnw, lnb, fc2w, fc2b, out);
}

// round 4
// speedup vs baseline: 4.1345x; 4.1345x over previous
#include <cuda_runtime.h>
#include <cuda_bf16.h>
#include <cstdint>

// G=1024 groups (1 CTA each), K=16 agents, T=32, D=64.
// out[n,t,0:64]=group mean of h ; out[n,t,64:128]=h ; h=fc2(relu(LN(fc1(x))))
// GEMMs: mma.sync m16n8k16 bf16, 3-term hi/lo split (~1e-5 precision).
#define GRPS 1024

// smem byte offsets
#define OFF_W1H 0
#define OFF_W1L 8192
#define OFF_W2H 16384
#define OFF_W2L 24576
#define OFF_AH  32768      // 128 rows x 128B bf16, SW-chunk swizzle
#define OFF_AL  49152
#define OFF_B1  65536
#define OFF_B2  65792
#define OFF_LNW 66048
#define OFF_LNB 66304
#define SMEM_BYTES 66560
// post-loop aliases:
#define OFF_RED   OFF_AH   // [128][64] f32 (256B rows, chunk-swizzled)
#define OFF_MEANS OFF_W1H  // [32][64] f32

__device__ __forceinline__ uint32_t smem_u32(const void* p) {
    uint32_t a;
    asm("{ .reg .u64 t; cvta.to.shared.u64 t, %1; cvt.u32.u64 %0, t; }" : "=r"(a) : "l"(p));
    return a;
}
// pack {lo, hi} floats -> bf16x2 (lo in low half / first in memory)
__device__ __forceinline__ uint32_t bf2pack(float lo, float hi) {
    uint32_t r; asm("cvt.rn.bf16x2.f32 %0, %1, %2;" : "=r"(r) : "f"(hi), "f"(lo)); return r;
}
__device__ __forceinline__ void ldmx4(uint32_t addr, uint32_t* r) {
    asm volatile("ldmatrix.sync.aligned.m8n8.x4.shared.b16 {%0,%1,%2,%3}, [%4];"
                 : "=r"(r[0]), "=r"(r[1]), "=r"(r[2]), "=r"(r[3]) : "r"(addr));
}
__device__ __forceinline__ void mma_bf16(float* c, const uint32_t* a,
                                         uint32_t b0, uint32_t b1) {
    asm volatile(
        "mma.sync.aligned.m16n8k16.row.col.f32.bf16.bf16.f32 "
        "{%0,%1,%2,%3}, {%4,%5,%6,%7}, {%8,%9}, {%0,%1,%2,%3};"
        : "+f"(c[0]), "+f"(c[1]), "+f"(c[2]), "+f"(c[3])
        : "r"(a[0]), "r"(a[1]), "r"(a[2]), "r"(a[3]), "r"(b0), "r"(b1));
}

// split 8 consecutive fp32 -> bf16 hi chunk (16B) + lo chunk (16B), swizzled store
__device__ __forceinline__ void split_store8(char* sm, int offH, int offL,
                                             int row, int ch, float4 a, float4 b) {
    float f[8] = {a.x, a.y, a.z, a.w, b.x, b.y, b.z, b.w};
    float fh[8];
    #pragma unroll
    for (int i = 0; i < 8; i++) fh[i] = __bfloat162float(__float2bfloat16(f[i]));
    uint4 vh, vl;
    vh.x = bf2pack(fh[0], fh[1]); vh.y = bf2pack(fh[2], fh[3]);
    vh.z = bf2pack(fh[4], fh[5]); vh.w = bf2pack(fh[6], fh[7]);
    vl.x = bf2pack(f[0]-fh[0], f[1]-fh[1]); vl.y = bf2pack(f[2]-fh[2], f[3]-fh[3]);
    vl.z = bf2pack(f[4]-fh[4], f[5]-fh[5]); vl.w = bf2pack(f[6]-fh[6], f[7]-fh[7]);
    int bo = row * 128 + ((ch ^ (row & 7)) << 4);
    *(uint4*)(sm + offH + bo) = vh;
    *(uint4*)(sm + offL + bo) = vl;
}

// 16x64 stripe GEMM vs 64x64 weights, 3 split terms. Addresses are per-lane bases.
__device__ __forceinline__ void gemm64(uint32_t aH, uint32_t aL,
                                       uint32_t wH, uint32_t wL,
                                       uint32_t lhalf, uint32_t lxor,
                                       float c[8][4]) {
    #pragma unroll
    for (int kk = 0; kk < 4; kk++) {
        uint32_t co = ((((uint32_t)(kk << 1) + lhalf) ^ lxor) << 4);
        uint32_t ah[4], al[4];
        ldmx4(aH + co, ah);
        ldmx4(aL + co, al);
        #pragma unroll
        for (int np = 0; np < 4; np++) {
            uint32_t bh[4], bl[4];
            ldmx4(wH + np * 2048 + co, bh);
            ldmx4(wL + np * 2048 + co, bl);
            mma_bf16(c[2*np],   ah, bh[0], bh[2]);
            mma_bf16(c[2*np+1], ah, bh[1], bh[3]);
            mma_bf16(c[2*np],   ah, bl[0], bl[2]);
            mma_bf16(c[2*np+1], ah, bl[1], bl[3]);
            mma_bf16(c[2*np],   al, bh[0], bh[2]);
            mma_bf16(c[2*np+1], al, bh[1], bh[3]);
        }
    }
}

__global__ void __launch_bounds__(256, 2)
subgraph_mma_kernel(const float* __restrict__ x,
                    const float* __restrict__ w1g, const float* __restrict__ b1g,
                    const float* __restrict__ lnwg, const float* __restrict__ lnbg,
                    const float* __restrict__ w2g, const float* __restrict__ b2g,
                    float* __restrict__ out) {
    extern __shared__ char sm[];
    const uint32_t smb = smem_u32(sm);
    const int tid = threadIdx.x, wid = tid >> 5, lane = tid & 31;
    const int g = blockIdx.x;

    // ---- stage weights (bf16 hi/lo, swizzled) + biases ----
    #pragma unroll
    for (int v = 0; v < 2; v++) {
        int lin = tid + v * 256;          // 0..511 : row 0..63, ch 0..7
        int row = lin >> 3, ch = lin & 7;
        const float4* p1 = (const float4*)(w1g + row * 64 + ch * 8);
        const float4* p2 = (const float4*)(w2g + row * 64 + ch * 8);
        split_store8(sm, OFF_W1H, OFF_W1L, row, ch, p1[0], p1[1]);
        split_store8(sm, OFF_W2H, OFF_W2L, row, ch, p2[0], p2[1]);
    }
    if (tid < 64) {
        ((float*)(sm + OFF_B1))[tid]  = b1g[tid];
        ((float*)(sm + OFF_B2))[tid]  = b2g[tid];
        ((float*)(sm + OFF_LNW))[tid] = lnwg[tid];
        ((float*)(sm + OFF_LNB))[tid] = lnbg[tid];
    }
    __syncthreads();

    // per-lane ldmatrix geometry (A and B share the same pattern)
    const int r0 = wid * 16;
    const uint32_t lrow  = (uint32_t)((((lane >> 3) & 1) << 3) + (lane & 7));
    const uint32_t lhalf = (uint32_t)(lane >> 4);
    const uint32_t lxor  = (uint32_t)(lane & 7);
    const uint32_t aH  = smb + OFF_AH  + (r0 + lrow) * 128;
    const uint32_t aL  = smb + OFF_AL  + (r0 + lrow) * 128;
    const uint32_t w1H = smb + OFF_W1H + lrow * 128;
    const uint32_t w1L = smb + OFF_W1L + lrow * 128;
    const uint32_t w2H = smb + OFF_W2H + lrow * 128;
    const uint32_t w2L = smb + OFF_W2L + lrow * 128;

    const int i0 = lane >> 2, m = lane & 3;
    const float* xg   = x   + (size_t)g * (512 * 64);
    float*       outg = out + (size_t)g * (512 * 128);
    const float2* b1v = (const float2*)(sm + OFF_B1);
    const float2* b2v = (const float2*)(sm + OFF_B2);
    const float2* lw2 = (const float2*)(sm + OFF_LNW);
    const float2* lb2 = (const float2*)(sm + OFF_LNB);

    float rs[32];
    #pragma unroll
    for (int i = 0; i < 32; i++) rs[i] = 0.f;

    #pragma unroll 1
    for (int mt = 0; mt < 4; mt++) {
        // ---- stage this warp's 16 x-rows into AH/AL ----
        #pragma unroll
        for (int u = 0; u < 4; u++) {
            int lin = u * 32 + lane;
            int row = r0 + (lin >> 3), ch = lin & 7;
            const float4* p = (const float4*)(xg + (size_t)(mt * 128 + row) * 64 + ch * 8);
            split_store8(sm, OFF_AH, OFF_AL, row, ch, p[0], p[1]);
        }
        __syncwarp();

        // ---- GEMM1 ----
        float c[8][4];
        #pragma unroll
        for (int i = 0; i < 8; i++)
            #pragma unroll
            for (int j = 0; j < 4; j++) c[i][j] = 0.f;
        gemm64(aH, aL, w1H, w1L, lhalf, lxor, c);

        // ---- bias + LayerNorm stats (rows r0+i0 and r0+i0+8) ----
        float h[8][4], s0 = 0.f, q0 = 0.f, s1 = 0.f, q1 = 0.f;
        #pragma unroll
        for (int n8 = 0; n8 < 8; n8++) {
            float2 bb = b1v[n8 * 4 + m];
            h[n8][0] = c[n8][0] + bb.x; h[n8][1] = c[n8][1] + bb.y;
            h[n8][2] = c[n8][2] + bb.x; h[n8][3] = c[n8][3] + bb.y;
            s0 += h[n8][0] + h[n8][1]; q0 += h[n8][0]*h[n8][0] + h[n8][1]*h[n8][1];
            s1 += h[n8][2] + h[n8][3]; q1 += h[n8][2]*h[n8][2] + h[n8][3]*h[n8][3];
        }
        s0 += __shfl_xor_sync(0xffffffffu, s0, 1); s0 += __shfl_xor_sync(0xffffffffu, s0, 2);
        q0 += __shfl_xor_sync(0xffffffffu, q0, 1); q0 += __shfl_xor_sync(0xffffffffu, q0, 2);
        s1 += __shfl_xor_sync(0xffffffffu, s1, 1); s1 += __shfl_xor_sync(0xffffffffu, s1, 2);
        q1 += __shfl_xor_sync(0xffffffffu, q1, 1); q1 += __shfl_xor_sync(0xffffffffu, q1, 2);
        float mu0 = s0 * (1.f/64.f), var0 = q0 * (1.f/64.f) - mu0*mu0;
        float mu1 = s1 * (1.f/64.f), var1 = q1 * (1.f/64.f) - mu1*mu1;
        float inv0 = rsqrtf(var0 + 1e-5f), inv1 = rsqrtf(var1 + 1e-5f);

        // ---- LN*w+b, ReLU, hi/lo split, store act back into AH/AL ----
        const int rb0 = (r0 + i0) * 128, rb1 = (r0 + i0 + 8) * 128;
        #pragma unroll
        for (int n8 = 0; n8 < 8; n8++) {
            float2 lwv = lw2[n8 * 4 + m], lbv = lb2[n8 * 4 + m];
            float a00 = fmaxf(fmaf((h[n8][0] - mu0) * inv0, lwv.x, lbv.x), 0.f);
            float a01 = fmaxf(fmaf((h[n8][1] - mu0) * inv0, lwv.y, lbv.y), 0.f);
            float a10 = fmaxf(fmaf((h[n8][2] - mu1) * inv1, lwv.x, lbv.x), 0.f);
            float a11 = fmaxf(fmaf((h[n8][3] - mu1) * inv1, lwv.y, lbv.y), 0.f);
            float h00 = __bfloat162float(__float2bfloat16(a00));
            float h01 = __bfloat162float(__float2bfloat16(a01));
            float h10 = __bfloat162float(__float2bfloat16(a10));
            float h11 = __bfloat162float(__float2bfloat16(a11));
            uint32_t off = (uint32_t)(((n8 ^ i0) << 4) + m * 4);
            *(uint32_t*)(sm + OFF_AH + rb0 + off) = bf2pack(h00, h01);
            *(uint32_t*)(sm + OFF_AL + rb0 + off) = bf2pack(a00 - h00, a01 - h01);
            *(uint32_t*)(sm + OFF_AH + rb1 + off) = bf2pack(h10, h11);
            *(uint32_t*)(sm + OFF_AL + rb1 + off) = bf2pack(a10 - h10, a11 - h11);
        }
        __syncwarp();

        // ---- GEMM2 ----
        #pragma unroll
        for (int i = 0; i < 8; i++)
            #pragma unroll
            for (int j = 0; j < 4; j++) c[i][j] = 0.f;
        gemm64(aH, aL, w2H, w2L, lhalf, lxor, c);

        // ---- bias, agent-sum accumulate, direct h store ----
        #pragma unroll
        for (int n8 = 0; n8 < 8; n8++) {
            float2 bb = b2v[n8 * 4 + m];
            float v00 = c[n8][0] + bb.x, v01 = c[n8][1] + bb.y;
            float v10 = c[n8][2] + bb.x, v11 = c[n8][3] + bb.y;
            rs[n8*4+0] += v00; rs[n8*4+1] += v01;
            rs[n8*4+2] += v10; rs[n8*4+3] += v11;
            int col0 = n8 * 8 + m * 2;
            *(float2*)(outg + (size_t)(mt*128 + r0 + i0)     * 128 + 64 + col0) = make_float2(v00, v01);
            *(float2*)(outg + (size_t)(mt*128 + r0 + i0 + 8) * 128 + 64 + col0) = make_float2(v10, v11);
        }
    }

    // ---- cross-warp agent-sum reduction ----
    __syncthreads();
    #pragma unroll
    for (int n8 = 0; n8 < 8; n8++) {
        #pragma unroll
        for (int rr = 0; rr < 2; rr++) {
            int row = r0 + i0 + rr * 8;
            int c16 = n8 * 2 + (m >> 1);
            uint32_t byte = (uint32_t)(row * 256 + ((c16 ^ (row & 15)) << 4) + (m & 1) * 8);
            *(float2*)(sm + OFF_RED + byte) =
                make_float2(rs[n8*4 + rr*2], rs[n8*4 + rr*2 + 1]);
        }
    }
    __syncthreads();
    {
        int t = tid >> 3, c0 = (tid & 7) * 8;
        float* means = (float*)(sm + OFF_MEANS);
        #pragma unroll
        for (int e = 0; e < 8; e++) {
            int cc = c0 + e;
            float ssum = 0.f;
            #pragma unroll
            for (int a = 0; a < 4; a++) {
                int r = t + a * 32;
                ssum += *(const float*)(sm + OFF_RED + r * 256
                         + (((cc >> 2) ^ (r & 15)) << 4) + (cc & 3) * 4);
            }
            means[t * 64 + cc] = ssum * 0.0625f;
        }
    }
    __syncthreads();
    // ---- broadcast group means to all 16 agents ----
    #pragma unroll 1
    for (int ag = 0; ag < 16; ag++) {
        #pragma unroll
        for (int v = 0; v < 2; v++) {
            int f = tid + v * 256;
            int t = f >> 4, c16 = f & 15;
            float4 mv = *(const float4*)(sm + OFF_MEANS + (t * 64 + c16 * 4) * 4);
            *(float4*)(outg + (size_t)(ag * 32 + t) * 128 + c16 * 4) = mv;
        }
    }
}

extern "C" void kernel_launch(void* const* d_in, const int* in_sizes, int n_in,
                              void* d_out, int out_size) {
    const float* x    = (const float*)d_in[0];
    const float* fc1w = (const float*)d_in[3];
    const float* fc1b = (const float*)d_in[4];
    const float* lnw  = (const float*)d_in[5];
    const float* lnb  = (const float*)d_in[6];
    const float* fc2w = (const float*)d_in[7];
    const float* fc2b = (const float*)d_in[8];
    float* out = (float*)d_out;

    cudaFuncSetAttribute(subgraph_mma_kernel,
                         cudaFuncAttributeMaxDynamicSharedMemorySize, SMEM_BYTES);
    subgraph_mma_kernel<<<GRPS, 256, SMEM_BYTES>>>(x, fc1w, fc1b, lnw, lnb, fc2w, fc2b, out);
}

// round 5
// speedup vs baseline: 4.1713x; 1.0089x over previous
#include <cuda_runtime.h>
#include <cuda_bf16.h>
#include <cstdint>

// G=1024 groups (1 CTA each), K=16 agents, T=32, D=64.
// out[n,t,0:64]=group mean of h ; out[n,t,64:128]=h ; h=fc2(relu(LN(fc1(x))))
// GEMMs: mma.sync m16n8k16 bf16, 3-term hi/lo split.
// A fragments: GEMM1 from direct gmem LDG; GEMM2 from GEMM1 C-fragments (register reuse).
#define GRPS 1024

// smem byte offsets
#define OFF_W1H 0
#define OFF_W1L 8192
#define OFF_W2H 16384
#define OFF_W2L 24576
#define OFF_B1  32768
#define OFF_B2  33024
#define OFF_LNW 33280
#define OFF_LNB 33536
#define SMEM_BYTES 33792
// post-loop aliases (weights dead after last GEMM2):
#define OFF_RED   0        // [128 rows][64 cols] f32, 256B rows, chunk-swizzled (32KB)
#define OFF_MEANS 0        // [32][64] f32 (8KB), written after RED is consumed

__device__ __forceinline__ uint32_t smem_u32(const void* p) {
    uint32_t a;
    asm("{ .reg .u64 t; cvta.to.shared.u64 t, %1; cvt.u32.u64 %0, t; }" : "=r"(a) : "l"(p));
    return a;
}
// pack {lo, hi} floats -> bf16x2 (lo in low half / first in memory)
__device__ __forceinline__ uint32_t bf2pack(float lo, float hi) {
    uint32_t r; asm("cvt.rn.bf16x2.f32 %0, %1, %2;" : "=r"(r) : "f"(hi), "f"(lo)); return r;
}
__device__ __forceinline__ void ldmx4(uint32_t addr, uint32_t* r) {
    asm volatile("ldmatrix.sync.aligned.m8n8.x4.shared.b16 {%0,%1,%2,%3}, [%4];"
                 : "=r"(r[0]), "=r"(r[1]), "=r"(r[2]), "=r"(r[3]) : "r"(addr));
}
__device__ __forceinline__ void mma_bf16(float* c, const uint32_t* a,
                                         uint32_t b0, uint32_t b1) {
    asm volatile(
        "mma.sync.aligned.m16n8k16.row.col.f32.bf16.bf16.f32 "
        "{%0,%1,%2,%3}, {%4,%5,%6,%7}, {%8,%9}, {%0,%1,%2,%3};"
        : "+f"(c[0]), "+f"(c[1]), "+f"(c[2]), "+f"(c[3])
        : "r"(a[0]), "r"(a[1]), "r"(a[2]), "r"(a[3]), "r"(b0), "r"(b1));
}
// split two f32 into bf16-hi pack + bf16-lo pack
__device__ __forceinline__ void split2(float x0, float x1, uint32_t& hi, uint32_t& lo) {
    float h0 = __bfloat162float(__float2bfloat16(x0));
    float h1 = __bfloat162float(__float2bfloat16(x1));
    hi = bf2pack(h0, h1);
    lo = bf2pack(x0 - h0, x1 - h1);
}

// split 8 consecutive fp32 -> bf16 hi chunk (16B) + lo chunk (16B), swizzled store
__device__ __forceinline__ void split_store8(char* sm, int offH, int offL,
                                             int row, int ch, float4 a, float4 b) {
    float f[8] = {a.x, a.y, a.z, a.w, b.x, b.y, b.z, b.w};
    uint4 vh, vl;
    split2(f[0], f[1], vh.x, vl.x); split2(f[2], f[3], vh.y, vl.y);
    split2(f[4], f[5], vh.z, vl.z); split2(f[6], f[7], vh.w, vl.w);
    int bo = row * 128 + ((ch ^ (row & 7)) << 4);
    *(uint4*)(sm + offH + bo) = vh;
    *(uint4*)(sm + offL + bo) = vl;
}

// 16x64 stripe GEMM vs 64x64 weights, register A, 3 split terms.
__device__ __forceinline__ void gemm64r(const uint32_t ah[4][4], const uint32_t al[4][4],
                                        uint32_t wH, uint32_t wL,
                                        uint32_t lhalf, uint32_t lxor,
                                        float c[8][4]) {
    #pragma unroll
    for (int kk = 0; kk < 4; kk++) {
        uint32_t co = ((((uint32_t)(kk << 1) + lhalf) ^ lxor) << 4);
        #pragma unroll
        for (int np = 0; np < 4; np++) {
            uint32_t bh[4], bl[4];
            ldmx4(wH + np * 2048 + co, bh);
            ldmx4(wL + np * 2048 + co, bl);
            mma_bf16(c[2*np],   ah[kk], bh[0], bh[2]);
            mma_bf16(c[2*np+1], ah[kk], bh[1], bh[3]);
            mma_bf16(c[2*np],   ah[kk], bl[0], bl[2]);
            mma_bf16(c[2*np+1], ah[kk], bl[1], bl[3]);
            mma_bf16(c[2*np],   al[kk], bh[0], bh[2]);
            mma_bf16(c[2*np+1], al[kk], bh[1], bh[3]);
        }
    }
}

__global__ void __launch_bounds__(256, 2)
subgraph_mma_kernel(const float* __restrict__ x,
                    const float* __restrict__ w1g, const float* __restrict__ b1g,
                    const float* __restrict__ lnwg, const float* __restrict__ lnbg,
                    const float* __restrict__ w2g, const float* __restrict__ b2g,
                    float* __restrict__ out) {
    extern __shared__ char sm[];
    const uint32_t smb = smem_u32(sm);
    const int tid = threadIdx.x, wid = tid >> 5, lane = tid & 31;
    const int g = blockIdx.x;

    // ---- stage weights (bf16 hi/lo, swizzled) + biases ----
    #pragma unroll
    for (int v = 0; v < 2; v++) {
        int lin = tid + v * 256;          // 0..511 : row 0..63, ch 0..7
        int row = lin >> 3, ch = lin & 7;
        const float4* p1 = (const float4*)(w1g + row * 64 + ch * 8);
        const float4* p2 = (const float4*)(w2g + row * 64 + ch * 8);
        split_store8(sm, OFF_W1H, OFF_W1L, row, ch, p1[0], p1[1]);
        split_store8(sm, OFF_W2H, OFF_W2L, row, ch, p2[0], p2[1]);
    }
    if (tid < 64) {
        ((float*)(sm + OFF_B1))[tid]  = b1g[tid];
        ((float*)(sm + OFF_B2))[tid]  = b2g[tid];
        ((float*)(sm + OFF_LNW))[tid] = lnwg[tid];
        ((float*)(sm + OFF_LNB))[tid] = lnbg[tid];
    }
    __syncthreads();

    const int r0 = wid * 16;
    const uint32_t lrow  = (uint32_t)((((lane >> 3) & 1) << 3) + (lane & 7));
    const uint32_t lhalf = (uint32_t)(lane >> 4);
    const uint32_t lxor  = (uint32_t)(lane & 7);
    const uint32_t w1H = smb + OFF_W1H + lrow * 128;
    const uint32_t w1L = smb + OFF_W1L + lrow * 128;
    const uint32_t w2H = smb + OFF_W2H + lrow * 128;
    const uint32_t w2L = smb + OFF_W2L + lrow * 128;

    const int i0 = lane >> 2, m = lane & 3;
    const float* xg   = x   + (size_t)g * (512 * 64);
    float*       outg = out + (size_t)g * (512 * 128);
    const float2* b1v = (const float2*)(sm + OFF_B1);
    const float2* b2v = (const float2*)(sm + OFF_B2);
    const float2* lw2 = (const float2*)(sm + OFF_LNW);
    const float2* lb2 = (const float2*)(sm + OFF_LNB);

    float rs[32];
    #pragma unroll
    for (int i = 0; i < 32; i++) rs[i] = 0.f;

    #pragma unroll 1
    for (int mt = 0; mt < 4; mt++) {
        const int rowA = mt * 128 + r0 + i0;
        const float* pa = xg + (size_t)rowA * 64;
        const float* pb = pa + 8 * 64;

        // ---- build GEMM1 A fragments straight from gmem ----
        float2 xv[2][4][2];
        #pragma unroll
        for (int kk = 0; kk < 4; kk++) {
            #pragma unroll
            for (int j = 0; j < 2; j++) {
                int col = kk * 16 + j * 8 + m * 2;
                xv[0][kk][j] = *(const float2*)(pa + col);
                xv[1][kk][j] = *(const float2*)(pb + col);
            }
        }
        uint32_t ah[4][4], al[4][4];
        #pragma unroll
        for (int kk = 0; kk < 4; kk++) {
            split2(xv[0][kk][0].x, xv[0][kk][0].y, ah[kk][0], al[kk][0]);
            split2(xv[1][kk][0].x, xv[1][kk][0].y, ah[kk][1], al[kk][1]);
            split2(xv[0][kk][1].x, xv[0][kk][1].y, ah[kk][2], al[kk][2]);
            split2(xv[1][kk][1].x, xv[1][kk][1].y, ah[kk][3], al[kk][3]);
        }

        // ---- GEMM1 ----
        float c[8][4];
        #pragma unroll
        for (int i = 0; i < 8; i++)
            #pragma unroll
            for (int j = 0; j < 4; j++) c[i][j] = 0.f;
        gemm64r(ah, al, w1H, w1L, lhalf, lxor, c);

        // ---- bias + LayerNorm stats (rows i0, i0+8 of the stripe) ----
        float h[8][4], s0 = 0.f, q0 = 0.f, s1 = 0.f, q1 = 0.f;
        #pragma unroll
        for (int n8 = 0; n8 < 8; n8++) {
            float2 bb = b1v[n8 * 4 + m];
            h[n8][0] = c[n8][0] + bb.x; h[n8][1] = c[n8][1] + bb.y;
            h[n8][2] = c[n8][2] + bb.x; h[n8][3] = c[n8][3] + bb.y;
            s0 += h[n8][0] + h[n8][1]; q0 += h[n8][0]*h[n8][0] + h[n8][1]*h[n8][1];
            s1 += h[n8][2] + h[n8][3]; q1 += h[n8][2]*h[n8][2] + h[n8][3]*h[n8][3];
        }
        s0 += __shfl_xor_sync(0xffffffffu, s0, 1); s0 += __shfl_xor_sync(0xffffffffu, s0, 2);
        q0 += __shfl_xor_sync(0xffffffffu, q0, 1); q0 += __shfl_xor_sync(0xffffffffu, q0, 2);
        s1 += __shfl_xor_sync(0xffffffffu, s1, 1); s1 += __shfl_xor_sync(0xffffffffu, s1, 2);
        q1 += __shfl_xor_sync(0xffffffffu, q1, 1); q1 += __shfl_xor_sync(0xffffffffu, q1, 2);
        float mu0 = s0 * (1.f/64.f), var0 = q0 * (1.f/64.f) - mu0*mu0;
        float mu1 = s1 * (1.f/64.f), var1 = q1 * (1.f/64.f) - mu1*mu1;
        float inv0 = rsqrtf(var0 + 1e-5f), inv1 = rsqrtf(var1 + 1e-5f);

        // ---- LN*w+b, ReLU, split -> GEMM2 A fragments (pure registers) ----
        #pragma unroll
        for (int n8 = 0; n8 < 8; n8++) {
            float2 lwv = lw2[n8 * 4 + m], lbv = lb2[n8 * 4 + m];
            float a00 = fmaxf(fmaf((h[n8][0] - mu0) * inv0, lwv.x, lbv.x), 0.f);
            float a01 = fmaxf(fmaf((h[n8][1] - mu0) * inv0, lwv.y, lbv.y), 0.f);
            float a10 = fmaxf(fmaf((h[n8][2] - mu1) * inv1, lwv.x, lbv.x), 0.f);
            float a11 = fmaxf(fmaf((h[n8][3] - mu1) * inv1, lwv.y, lbv.y), 0.f);
            int kk = n8 >> 1, hf = (n8 & 1) * 2;
            split2(a00, a01, ah[kk][hf + 0], al[kk][hf + 0]);
            split2(a10, a11, ah[kk][hf + 1], al[kk][hf + 1]);
        }

        // ---- GEMM2 ----
        #pragma unroll
        for (int i = 0; i < 8; i++)
            #pragma unroll
            for (int j = 0; j < 4; j++) c[i][j] = 0.f;
        gemm64r(ah, al, w2H, w2L, lhalf, lxor, c);

        // ---- bias, agent-sum accumulate, direct h store ----
        #pragma unroll
        for (int n8 = 0; n8 < 8; n8++) {
            float2 bb = b2v[n8 * 4 + m];
            float v00 = c[n8][0] + bb.x, v01 = c[n8][1] + bb.y;
            float v10 = c[n8][2] + bb.x, v11 = c[n8][3] + bb.y;
            rs[n8*4+0] += v00; rs[n8*4+1] += v01;
            rs[n8*4+2] += v10; rs[n8*4+3] += v11;
            int col0 = n8 * 8 + m * 2;
            *(float2*)(outg + (size_t)rowA       * 128 + 64 + col0) = make_float2(v00, v01);
            *(float2*)(outg + (size_t)(rowA + 8) * 128 + 64 + col0) = make_float2(v10, v11);
        }
    }

    // ---- cross-warp agent-sum reduction (RED aliases dead weight tiles) ----
    __syncthreads();
    #pragma unroll
    for (int n8 = 0; n8 < 8; n8++) {
        #pragma unroll
        for (int rr = 0; rr < 2; rr++) {
            int row = r0 + i0 + rr * 8;
            int c16 = n8 * 2 + (m >> 1);
            uint32_t byte = (uint32_t)(row * 256 + ((c16 ^ (row & 15)) << 4) + (m & 1) * 8);
            *(float2*)(sm + OFF_RED + byte) =
                make_float2(rs[n8*4 + rr*2], rs[n8*4 + rr*2 + 1]);
        }
    }
    __syncthreads();
    float mv[8];
    int tq = tid >> 3, cq = (tid & 7) * 8;
    #pragma unroll
    for (int e = 0; e < 8; e++) {
        int cc = cq + e;
        float ssum = 0.f;
        #pragma unroll
        for (int a = 0; a < 4; a++) {
            int r = tq + a * 32;
            ssum += *(const float*)(sm + OFF_RED + r * 256
                     + (((cc >> 2) ^ (r & 15)) << 4) + (cc & 3) * 4);
        }
        mv[e] = ssum * 0.0625f;
    }
    __syncthreads();
    {
        float* means = (float*)(sm + OFF_MEANS);
        #pragma unroll
        for (int e = 0; e < 8; e++) means[tq * 64 + cq + e] = mv[e];
    }
    __syncthreads();
    // ---- broadcast group means to all 16 agents ----
    #pragma unroll 1
    for (int ag = 0; ag < 16; ag++) {
        #pragma unroll
        for (int v = 0; v < 2; v++) {
            int f = tid + v * 256;
            int t = f >> 4, c16 = f & 15;
            float4 mvv = *(const float4*)(sm + OFF_MEANS + (t * 64 + c16 * 4) * 4);
            *(float4*)(outg + (size_t)(ag * 32 + t) * 128 + c16 * 4) = mvv;
        }
    }
}

extern "C" void kernel_launch(void* const* d_in, const int* in_sizes, int n_in,
                              void* d_out, int out_size) {
    const float* x    = (const float*)d_in[0];
    const float* fc1w = (const float*)d_in[3];
    const float* fc1b = (const float*)d_in[4];
    const float* lnw  = (const float*)d_in[5];
    const float* lnb  = (const float*)d_in[6];
    const float* fc2w = (const float*)d_in[7];
    const float* fc2b = (const float*)d_in[8];
    float* out = (float*)d_out;

    cudaFuncSetAttribute(subgraph_mma_kernel,
                         cudaFuncAttributeMaxDynamicSharedMemorySize, SMEM_BYTES);
    subgraph_mma_kernel<<<GRPS, 256, SMEM_BYTES>>>(x, fc1w, fc1b, lnw, lnb, fc2w, fc2b, out);
}

// round 6
// speedup vs baseline: 4.4693x; 1.0714x over previous
#include <cuda_runtime.h>
#include <cuda_bf16.h>
#include <cstdint>

// G=1024 groups (1 CTA each), K=16 agents, T=32, D=64.
// out[n,t,0:64]=group mean of h ; out[n,t,64:128]=h ; h=fc2(relu(LN(fc1(x))))
// GEMMs: mma.sync m16n8k16 bf16, 3-term hi/lo split (truncation split, exact lo).
// A fragments: GEMM1 from gmem LDG (L1-prefetched); GEMM2 from GEMM1 C-fragments.
#define GRPS 1024

// smem byte offsets
#define OFF_W1H 0
#define OFF_W1L 8192
#define OFF_W2H 16384
#define OFF_W2L 24576
#define OFF_B1  32768
#define OFF_B2  33024
#define OFF_LNW 33280
#define OFF_LNB 33536
#define SMEM_BYTES 33792
// post-loop aliases (weights dead after last GEMM2):
#define OFF_RED   0        // [128 rows][64 cols] f32, 256B rows, chunk-swizzled (32KB)
#define OFF_MEANS 0        // [32][64] f32 (8KB), written after RED is consumed

__device__ __forceinline__ uint32_t smem_u32(const void* p) {
    uint32_t a;
    asm("{ .reg .u64 t; cvta.to.shared.u64 t, %1; cvt.u32.u64 %0, t; }" : "=r"(a) : "l"(p));
    return a;
}
// pack {lo, hi} floats -> bf16x2 (lo in low half / first in memory)
__device__ __forceinline__ uint32_t bf2pack(float lo, float hi) {
    uint32_t r; asm("cvt.rn.bf16x2.f32 %0, %1, %2;" : "=r"(r) : "f"(hi), "f"(lo)); return r;
}
__device__ __forceinline__ void ldmx4(uint32_t addr, uint32_t* r) {
    asm volatile("ldmatrix.sync.aligned.m8n8.x4.shared.b16 {%0,%1,%2,%3}, [%4];"
                 : "=r"(r[0]), "=r"(r[1]), "=r"(r[2]), "=r"(r[3]) : "r"(addr));
}
__device__ __forceinline__ void mma_bf16(float* c, const uint32_t* a,
                                         uint32_t b0, uint32_t b1) {
    asm volatile(
        "mma.sync.aligned.m16n8k16.row.col.f32.bf16.bf16.f32 "
        "{%0,%1,%2,%3}, {%4,%5,%6,%7}, {%8,%9}, {%0,%1,%2,%3};"
        : "+f"(c[0]), "+f"(c[1]), "+f"(c[2]), "+f"(c[3])
        : "r"(a[0]), "r"(a[1]), "r"(a[2]), "r"(a[3]), "r"(b0), "r"(b1));
}
// truncation split: hi = top-16 bits of each f32 (1 PRMT for the pack, LOP3 for
// the float); lo = (x - hi) rounded to bf16. hi+lo ≈ x to ~2^-17.
__device__ __forceinline__ void split2(float x0, float x1, uint32_t& hi, uint32_t& lo) {
    uint32_t u0 = __float_as_uint(x0), u1 = __float_as_uint(x1);
    hi = __byte_perm(u0, u1, 0x7632);
    float h0 = __uint_as_float(u0 & 0xffff0000u);
    float h1 = __uint_as_float(u1 & 0xffff0000u);
    lo = bf2pack(x0 - h0, x1 - h1);
}

// split 8 consecutive fp32 -> bf16 hi chunk (16B) + lo chunk (16B), swizzled store
__device__ __forceinline__ void split_store8(char* sm, int offH, int offL,
                                             int row, int ch, float4 a, float4 b) {
    float f[8] = {a.x, a.y, a.z, a.w, b.x, b.y, b.z, b.w};
    uint4 vh, vl;
    split2(f[0], f[1], vh.x, vl.x); split2(f[2], f[3], vh.y, vl.y);
    split2(f[4], f[5], vh.z, vl.z); split2(f[6], f[7], vh.w, vl.w);
    int bo = row * 128 + ((ch ^ (row & 7)) << 4);
    *(uint4*)(sm + offH + bo) = vh;
    *(uint4*)(sm + offL + bo) = vl;
}

// 16x64 stripe GEMM vs 64x64 weights, register A, 3 split terms.
__device__ __forceinline__ void gemm64r(const uint32_t ah[4][4], const uint32_t al[4][4],
                                        uint32_t wH, uint32_t wL,
                                        uint32_t lhalf, uint32_t lxor,
                                        float c[8][4]) {
    #pragma unroll
    for (int kk = 0; kk < 4; kk++) {
        uint32_t co = ((((uint32_t)(kk << 1) + lhalf) ^ lxor) << 4);
        #pragma unroll
        for (int np = 0; np < 4; np++) {
            uint32_t bh[4], bl[4];
            ldmx4(wH + np * 2048 + co, bh);
            ldmx4(wL + np * 2048 + co, bl);
            mma_bf16(c[2*np],   ah[kk], bh[0], bh[2]);
            mma_bf16(c[2*np+1], ah[kk], bh[1], bh[3]);
            mma_bf16(c[2*np],   ah[kk], bl[0], bl[2]);
            mma_bf16(c[2*np+1], ah[kk], bl[1], bl[3]);
            mma_bf16(c[2*np],   al[kk], bh[0], bh[2]);
            mma_bf16(c[2*np+1], al[kk], bh[1], bh[3]);
        }
    }
}

__global__ void __launch_bounds__(256, 2)
subgraph_mma_kernel(const float* __restrict__ x,
                    const float* __restrict__ w1g, const float* __restrict__ b1g,
                    const float* __restrict__ lnwg, const float* __restrict__ lnbg,
                    const float* __restrict__ w2g, const float* __restrict__ b2g,
                    float* __restrict__ out) {
    extern __shared__ char sm[];
    const uint32_t smb = smem_u32(sm);
    const int tid = threadIdx.x, wid = tid >> 5, lane = tid & 31;
    const int g = blockIdx.x;

    // ---- stage weights (bf16 hi/lo, swizzled) + biases ----
    #pragma unroll
    for (int v = 0; v < 2; v++) {
        int lin = tid + v * 256;          // 0..511 : row 0..63, ch 0..7
        int row = lin >> 3, ch = lin & 7;
        const float4* p1 = (const float4*)(w1g + row * 64 + ch * 8);
        const float4* p2 = (const float4*)(w2g + row * 64 + ch * 8);
        split_store8(sm, OFF_W1H, OFF_W1L, row, ch, p1[0], p1[1]);
        split_store8(sm, OFF_W2H, OFF_W2L, row, ch, p2[0], p2[1]);
    }
    if (tid < 64) {
        ((float*)(sm + OFF_B1))[tid]  = b1g[tid];
        ((float*)(sm + OFF_B2))[tid]  = b2g[tid];
        ((float*)(sm + OFF_LNW))[tid] = lnwg[tid];
        ((float*)(sm + OFF_LNB))[tid] = lnbg[tid];
    }
    __syncthreads();

    const int r0 = wid * 16;
    const uint32_t lrow  = (uint32_t)((((lane >> 3) & 1) << 3) + (lane & 7));
    const uint32_t lhalf = (uint32_t)(lane >> 4);
    const uint32_t lxor  = (uint32_t)(lane & 7);
    const uint32_t w1H = smb + OFF_W1H + lrow * 128;
    const uint32_t w1L = smb + OFF_W1L + lrow * 128;
    const uint32_t w2H = smb + OFF_W2H + lrow * 128;
    const uint32_t w2L = smb + OFF_W2L + lrow * 128;

    const int i0 = lane >> 2, m = lane & 3;
    const float* xg   = x   + (size_t)g * (512 * 64);
    float*       outg = out + (size_t)g * (512 * 128);
    const float2* b1v = (const float2*)(sm + OFF_B1);
    const float2* b2v = (const float2*)(sm + OFF_B2);
    const float2* lw2 = (const float2*)(sm + OFF_LNW);
    const float2* lb2 = (const float2*)(sm + OFF_LNB);

    // prefetch tile 0 (x lives in L2/L1 by the time we load it)
    asm volatile("prefetch.global.L1 [%0];" :: "l"(xg + (size_t)tid * 32));

    float rs[32];
    #pragma unroll
    for (int i = 0; i < 32; i++) rs[i] = 0.f;

    #pragma unroll 1
    for (int mt = 0; mt < 4; mt++) {
        const int rowA = mt * 128 + r0 + i0;
        const float* pa = xg + (size_t)rowA * 64;
        const float* pb = pa + 8 * 64;

        // ---- build GEMM1 A fragments straight from gmem ----
        float2 xv[2][4][2];
        #pragma unroll
        for (int kk = 0; kk < 4; kk++) {
            #pragma unroll
            for (int j = 0; j < 2; j++) {
                int col = kk * 16 + j * 8 + m * 2;
                xv[0][kk][j] = *(const float2*)(pa + col);
                xv[1][kk][j] = *(const float2*)(pb + col);
            }
        }
        // prefetch next tile while this tile's loads are in flight
        if (mt < 3)
            asm volatile("prefetch.global.L1 [%0];"
                         :: "l"(xg + (size_t)(mt + 1) * 128 * 64 + (size_t)tid * 32));

        uint32_t ah[4][4], al[4][4];
        #pragma unroll
        for (int kk = 0; kk < 4; kk++) {
            split2(xv[0][kk][0].x, xv[0][kk][0].y, ah[kk][0], al[kk][0]);
            split2(xv[1][kk][0].x, xv[1][kk][0].y, ah[kk][1], al[kk][1]);
            split2(xv[0][kk][1].x, xv[0][kk][1].y, ah[kk][2], al[kk][2]);
            split2(xv[1][kk][1].x, xv[1][kk][1].y, ah[kk][3], al[kk][3]);
        }

        // ---- GEMM1 ----
        float c[8][4];
        #pragma unroll
        for (int i = 0; i < 8; i++)
            #pragma unroll
            for (int j = 0; j < 4; j++) c[i][j] = 0.f;
        gemm64r(ah, al, w1H, w1L, lhalf, lxor, c);

        // ---- bias (in place) + LayerNorm stats ----
        float s0 = 0.f, q0 = 0.f, s1 = 0.f, q1 = 0.f;
        #pragma unroll
        for (int n8 = 0; n8 < 8; n8++) {
            float2 bb = b1v[n8 * 4 + m];
            c[n8][0] += bb.x; c[n8][1] += bb.y;
            c[n8][2] += bb.x; c[n8][3] += bb.y;
            s0 += c[n8][0] + c[n8][1]; q0 += c[n8][0]*c[n8][0] + c[n8][1]*c[n8][1];
            s1 += c[n8][2] + c[n8][3]; q1 += c[n8][2]*c[n8][2] + c[n8][3]*c[n8][3];
        }
        s0 += __shfl_xor_sync(0xffffffffu, s0, 1); s0 += __shfl_xor_sync(0xffffffffu, s0, 2);
        q0 += __shfl_xor_sync(0xffffffffu, q0, 1); q0 += __shfl_xor_sync(0xffffffffu, q0, 2);
        s1 += __shfl_xor_sync(0xffffffffu, s1, 1); s1 += __shfl_xor_sync(0xffffffffu, s1, 2);
        q1 += __shfl_xor_sync(0xffffffffu, q1, 1); q1 += __shfl_xor_sync(0xffffffffu, q1, 2);
        float mu0 = s0 * (1.f/64.f), var0 = q0 * (1.f/64.f) - mu0*mu0;
        float mu1 = s1 * (1.f/64.f), var1 = q1 * (1.f/64.f) - mu1*mu1;
        float inv0 = rsqrtf(var0 + 1e-5f), inv1 = rsqrtf(var1 + 1e-5f);

        // ---- LN*w+b, ReLU, split -> GEMM2 A fragments (pure registers) ----
        #pragma unroll
        for (int n8 = 0; n8 < 8; n8++) {
            float2 lwv = lw2[n8 * 4 + m], lbv = lb2[n8 * 4 + m];
            float a00 = fmaxf(fmaf((c[n8][0] - mu0) * inv0, lwv.x, lbv.x), 0.f);
            float a01 = fmaxf(fmaf((c[n8][1] - mu0) * inv0, lwv.y, lbv.y), 0.f);
            float a10 = fmaxf(fmaf((c[n8][2] - mu1) * inv1, lwv.x, lbv.x), 0.f);
            float a11 = fmaxf(fmaf((c[n8][3] - mu1) * inv1, lwv.y, lbv.y), 0.f);
            int kk = n8 >> 1, hf = (n8 & 1) * 2;
            split2(a00, a01, ah[kk][hf + 0], al[kk][hf + 0]);
            split2(a10, a11, ah[kk][hf + 1], al[kk][hf + 1]);
        }

        // ---- GEMM2 ----
        #pragma unroll
        for (int i = 0; i < 8; i++)
            #pragma unroll
            for (int j = 0; j < 4; j++) c[i][j] = 0.f;
        gemm64r(ah, al, w2H, w2L, lhalf, lxor, c);

        // ---- bias, agent-sum accumulate, direct h store ----
        #pragma unroll
        for (int n8 = 0; n8 < 8; n8++) {
            float2 bb = b2v[n8 * 4 + m];
            float v00 = c[n8][0] + bb.x, v01 = c[n8][1] + bb.y;
            float v10 = c[n8][2] + bb.x, v11 = c[n8][3] + bb.y;
            rs[n8*4+0] += v00; rs[n8*4+1] += v01;
            rs[n8*4+2] += v10; rs[n8*4+3] += v11;
            int col0 = n8 * 8 + m * 2;
            *(float2*)(outg + (size_t)rowA       * 128 + 64 + col0) = make_float2(v00, v01);
            *(float2*)(outg + (size_t)(rowA + 8) * 128 + 64 + col0) = make_float2(v10, v11);
        }
    }

    // ---- cross-warp agent-sum reduction (RED aliases dead weight tiles) ----
    __syncthreads();
    #pragma unroll
    for (int n8 = 0; n8 < 8; n8++) {
        #pragma unroll
        for (int rr = 0; rr < 2; rr++) {
            int row = r0 + i0 + rr * 8;
            int c16 = n8 * 2 + (m >> 1);
            uint32_t byte = (uint32_t)(row * 256 + ((c16 ^ (row & 15)) << 4) + (m & 1) * 8);
            *(float2*)(sm + OFF_RED + byte) =
                make_float2(rs[n8*4 + rr*2], rs[n8*4 + rr*2 + 1]);
        }
    }
    __syncthreads();
    float mv[8];
    int tq = tid >> 3, cq = (tid & 7) * 8;
    #pragma unroll
    for (int e = 0; e < 8; e++) {
        int cc = cq + e;
        float ssum = 0.f;
        #pragma unroll
        for (int a = 0; a < 4; a++) {
            int r = tq + a * 32;
            ssum += *(const float*)(sm + OFF_RED + r * 256
                     + (((cc >> 2) ^ (r & 15)) << 4) + (cc & 3) * 4);
        }
        mv[e] = ssum * 0.0625f;
    }
    __syncthreads();
    {
        float* means = (float*)(sm + OFF_MEANS);
        #pragma unroll
        for (int e = 0; e < 8; e++) means[tq * 64 + cq + e] = mv[e];
    }
    __syncthreads();
    // ---- broadcast group means to all 16 agents ----
    #pragma unroll 1
    for (int ag = 0; ag < 16; ag++) {
        #pragma unroll
        for (int v = 0; v < 2; v++) {
            int f = tid + v * 256;
            int t = f >> 4, c16 = f & 15;
            float4 mvv = *(const float4*)(sm + OFF_MEANS + (t * 64 + c16 * 4) * 4);
            *(float4*)(outg + (size_t)(ag * 32 + t) * 128 + c16 * 4) = mvv;
        }
    }
}

extern "C" void kernel_launch(void* const* d_in, const int* in_sizes, int n_in,
                              void* d_out, int out_size) {
    const float* x    = (const float*)d_in[0];
    const float* fc1w = (const float*)d_in[3];
    const float* fc1b = (const float*)d_in[4];
    const float* lnw  = (const float*)d_in[5];
    const float* lnb  = (const float*)d_in[6];
    const float* fc2w = (const float*)d_in[7];
    const float* fc2b = (const float*)d_in[8];
    float* out = (float*)d_out;

    cudaFuncSetAttribute(subgraph_mma_kernel,
                         cudaFuncAttributeMaxDynamicSharedMemorySize, SMEM_BYTES);
    subgraph_mma_kernel<<<GRPS, 256, SMEM_BYTES>>>(x, fc1w, fc1b, lnw, lnb, fc2w, fc2b, out);
}